// round 3
// baseline (speedup 1.0000x reference)
#include <cuda_runtime.h>
#include <cuda_bf16.h>

// ---------------------------------------------------------------------------
// GNN_23630910062676: 2-layer GCN
//   deg/norm -> h1 = x@W1 -> out1 = scatter(norm*h1) + b1 -> relu
//   -> h2 = out1@W2 -> out = scatter(norm*h2) + b2
// Push-based scatter with red.global.add.v4.f32 (vector L2 reductions).
// ---------------------------------------------------------------------------

#define N_NODES 50000
#define N_EDGES 800000
#define DIN  64
#define DHID 128
#define DOUT 64

// Scratch (allocation-free rule: __device__ globals)
__device__ float g_deg [N_NODES];
__device__ float g_dinv[N_NODES];
__device__ float g_H1  [N_NODES * DHID];   // x @ W1
__device__ float g_O1  [N_NODES * DHID];   // aggregated layer-1 output (pre-relu)
__device__ float g_H2  [N_NODES * DOUT];   // relu(O1) @ W2

// ---------------------------------------------------------------------------
__global__ void k_init_deg() {
    int i = blockIdx.x * blockDim.x + threadIdx.x;
    if (i < N_NODES) g_deg[i] = 1.0f;   // self-loop
}

__global__ void k_count_deg(const int* __restrict__ dst) {
    int e = blockIdx.x * blockDim.x + threadIdx.x;
    if (e < N_EDGES) atomicAdd(&g_deg[dst[e]], 1.0f);
}

__global__ void k_dinv() {
    int i = blockIdx.x * blockDim.x + threadIdx.x;
    if (i < N_NODES) g_dinv[i] = rsqrtf(g_deg[i]);   // deg >= 1 always
}

// ---------------------------------------------------------------------------
// GEMM1: H1[N,128] = x[N,64] @ W1[64,128]. 128 thr/block, 16 rows/block.
__global__ void k_gemm1(const float* __restrict__ x, const float* __restrict__ W) {
    __shared__ float sW[DIN * DHID];    // 32 KB
    __shared__ float sx[16 * DIN];      // 4 KB
    int t = threadIdx.x;
    for (int i = t; i < DIN * DHID; i += 128) sW[i] = W[i];
    int row0 = blockIdx.x * 16;
    int nrows = min(16, N_NODES - row0);
    for (int i = t; i < nrows * DIN; i += 128) sx[i] = x[row0 * DIN + i];
    __syncthreads();
    for (int r = 0; r < nrows; r++) {
        float acc = 0.f;
        #pragma unroll
        for (int k = 0; k < DIN; k++) acc = fmaf(sx[r * DIN + k], sW[k * DHID + t], acc);
        g_H1[(row0 + r) * DHID + t] = acc;
    }
}

// init O1 with bias + self-loop contribution (dinv[i]^2 * h1[i])
__global__ void k_selfbias1(const float* __restrict__ b1) {
    int idx = blockIdx.x * blockDim.x + threadIdx.x;
    if (idx >= N_NODES * DHID) return;
    int row = idx >> 7;          // /128
    int f   = idx & (DHID - 1);
    float di = g_dinv[row];
    g_O1[idx] = b1[f] + g_H1[idx] * di * di;
}

__device__ __forceinline__ void red_v4(float* p, float4 v) {
    asm volatile("red.global.add.v4.f32 [%0], {%1,%2,%3,%4};"
                 :: "l"(p), "f"(v.x), "f"(v.y), "f"(v.z), "f"(v.w) : "memory");
}

// Scatter layer 1: one warp per edge, 128 floats = 32 x float4
__global__ void k_scatter1(const int* __restrict__ src, const int* __restrict__ dst) {
    int g = blockIdx.x * blockDim.x + threadIdx.x;
    int e = g >> 5;
    if (e >= N_EDGES) return;
    int lane = g & 31;
    int s = src[e], d = dst[e];
    float norm = g_dinv[s] * g_dinv[d];
    float4 v = reinterpret_cast<const float4*>(g_H1 + (size_t)s * DHID)[lane];
    v.x *= norm; v.y *= norm; v.z *= norm; v.w *= norm;
    red_v4(g_O1 + (size_t)d * DHID + lane * 4, v);
}

// ---------------------------------------------------------------------------
// GEMM2: H2[N,64] = relu(O1)[N,128] @ W2[128,64]. relu fused into smem load.
__global__ void k_gemm2(const float* __restrict__ W) {
    __shared__ float sW[DHID * DOUT];   // 32 KB
    __shared__ float sx[16 * DHID];     // 8 KB
    int t = threadIdx.x;                // 128
    for (int i = t; i < DHID * DOUT; i += 128) sW[i] = W[i];
    int row0 = blockIdx.x * 16;
    int nrows = min(16, N_NODES - row0);
    for (int i = t; i < nrows * DHID; i += 128) {
        float v = g_O1[row0 * DHID + i];
        sx[i] = v > 0.f ? v : 0.f;
    }
    __syncthreads();
    int col = t & 63;
    int rsub = t >> 6;                  // 0..1
    for (int r = rsub; r < nrows; r += 2) {
        float acc = 0.f;
        #pragma unroll
        for (int k = 0; k < DHID; k++) acc = fmaf(sx[r * DHID + k], sW[k * DOUT + col], acc);
        g_H2[(row0 + r) * DOUT + col] = acc;
    }
}

__global__ void k_selfbias2(const float* __restrict__ b2, float* __restrict__ out) {
    int idx = blockIdx.x * blockDim.x + threadIdx.x;
    if (idx >= N_NODES * DOUT) return;
    int row = idx >> 6;          // /64
    int f   = idx & (DOUT - 1);
    float di = g_dinv[row];
    out[idx] = b2[f] + g_H2[idx] * di * di;
}

// Scatter layer 2: half-warp per edge, 64 floats = 16 x float4
__global__ void k_scatter2(const int* __restrict__ src, const int* __restrict__ dst,
                           float* __restrict__ out) {
    int g = blockIdx.x * blockDim.x + threadIdx.x;
    int e = g >> 4;
    if (e >= N_EDGES) return;
    int l = g & 15;
    int s = src[e], d = dst[e];
    float norm = g_dinv[s] * g_dinv[d];
    float4 v = reinterpret_cast<const float4*>(g_H2 + (size_t)s * DOUT)[l];
    v.x *= norm; v.y *= norm; v.z *= norm; v.w *= norm;
    red_v4(out + (size_t)d * DOUT + l * 4, v);
}

// ---------------------------------------------------------------------------
extern "C" void kernel_launch(void* const* d_in, const int* in_sizes, int n_in,
                              void* d_out, int out_size) {
    const float* x    = (const float*)d_in[0];
    const int*   ei   = (const int*)d_in[1];     // [2, E]: src = ei, dst = ei + E
    const float* W1   = (const float*)d_in[2];
    const float* b1   = (const float*)d_in[3];
    const float* W2   = (const float*)d_in[4];
    const float* b2   = (const float*)d_in[5];
    float* out = (float*)d_out;

    const int* src = ei;
    const int* dst = ei + N_EDGES;

    // degrees + dinv
    k_init_deg <<<(N_NODES + 255) / 256, 256>>>();
    k_count_deg<<<(N_EDGES + 255) / 256, 256>>>(dst);
    k_dinv     <<<(N_NODES + 255) / 256, 256>>>();

    // layer 1
    k_gemm1    <<<(N_NODES + 15) / 16, 128>>>(x, W1);
    k_selfbias1<<<(N_NODES * DHID + 255) / 256, 256>>>(b1);
    {
        long long thr = (long long)N_EDGES * 32;
        k_scatter1<<<(unsigned)((thr + 255) / 256), 256>>>(src, dst);
    }

    // layer 2 (relu fused into gemm2 load)
    k_gemm2    <<<(N_NODES + 15) / 16, 128>>>(W2);
    k_selfbias2<<<(N_NODES * DOUT + 255) / 256, 256>>>(b2, out);
    {
        long long thr = (long long)N_EDGES * 16;
        k_scatter2<<<(unsigned)((thr + 255) / 256), 256>>>(src, dst, out);
    }
}

// round 5
// speedup vs baseline: 1.3693x; 1.3693x over previous
#include <cuda_runtime.h>
#include <cuda_bf16.h>

// ---------------------------------------------------------------------------
// GNN_23630910062676: 2-layer GCN, restructured:
//   deg/dinv -> AX = A_hat @ x (64-wide aggregate, cheap!)
//   H = relu(AX @ W1 + b1)
//   G = H @ W2 ; out = b2 + dinv^2*G + scatter(norm*G)
// Uses (A_hat X)W1 == A_hat(X W1) to aggregate the narrow tensor.
// ---------------------------------------------------------------------------

#define N_NODES 50000
#define N_EDGES 800000
#define DIN  64
#define DHID 128
#define DOUT 64

__device__ float g_deg [N_NODES];
__device__ float g_dinv[N_NODES];
__device__ float g_AX  [N_NODES * DIN];    // A_hat @ x
__device__ float g_H   [N_NODES * DHID];   // relu(AX@W1 + b1)
__device__ float g_G   [N_NODES * DOUT];   // H @ W2

// ---------------------------------------------------------------------------
__global__ void k_init_deg() {
    int i = blockIdx.x * blockDim.x + threadIdx.x;
    if (i < N_NODES) g_deg[i] = 1.0f;   // self-loop
}

__global__ void k_count_deg(const int* __restrict__ dst) {
    int e = blockIdx.x * blockDim.x + threadIdx.x;
    if (e < N_EDGES) atomicAdd(&g_deg[dst[e]], 1.0f);
}

__global__ void k_dinv() {
    int i = blockIdx.x * blockDim.x + threadIdx.x;
    if (i < N_NODES) g_dinv[i] = rsqrtf(g_deg[i]);
}

// AX init: self-loop term dinv^2 * x   (float4 vectorized)
__global__ void k_initAX(const float* __restrict__ x) {
    int q = blockIdx.x * blockDim.x + threadIdx.x;       // float4 index
    if (q >= N_NODES * (DIN / 4)) return;
    int row = q >> 4;                                    // /16 float4 per row
    float di = g_dinv[row];
    float s = di * di;
    float4 v = reinterpret_cast<const float4*>(x)[q];
    v.x *= s; v.y *= s; v.z *= s; v.w *= s;
    reinterpret_cast<float4*>(g_AX)[q] = v;
}

__device__ __forceinline__ void red_v4(float* p, float4 v) {
    asm volatile("red.global.add.v4.f32 [%0], {%1,%2,%3,%4};"
                 :: "l"(p), "f"(v.x), "f"(v.y), "f"(v.z), "f"(v.w) : "memory");
}

// Scatter x into AX: 16 lanes per edge (64 floats = 16 float4)
__global__ void k_scatterX(const float* __restrict__ x,
                           const int* __restrict__ src, const int* __restrict__ dst) {
    int g = blockIdx.x * blockDim.x + threadIdx.x;
    int e = g >> 4;
    if (e >= N_EDGES) return;
    int l = g & 15;
    int s = src[e], d = dst[e];
    float norm = g_dinv[s] * g_dinv[d];
    float4 v = reinterpret_cast<const float4*>(x + (size_t)s * DIN)[l];
    v.x *= norm; v.y *= norm; v.z *= norm; v.w *= norm;
    red_v4(g_AX + (size_t)d * DIN + l * 4, v);
}

// ---------------------------------------------------------------------------
// GEMM1: H[N,128] = relu(AX[N,64] @ W1[64,128] + b1)
// Block: 64 rows x 128 cols, 128 threads, each computes 8x8 register tile.
__global__ void __launch_bounds__(128) k_gemm1(const float* __restrict__ W1,
                                               const float* __restrict__ b1) {
    __shared__ float sA[DIN * 64];    // [k][row]  16 KB (transposed)
    __shared__ float sB[DIN * DHID];  // [k][col]  32 KB (W1 is already [k][col])
    int t = threadIdx.x;
    int row0 = blockIdx.x * 64;

    for (int i = t; i < DIN * DHID; i += 128) sB[i] = W1[i];
    for (int i = t; i < 64 * 16; i += 128) {       // 64 rows x 16 float4
        int r = i >> 4, kq = i & 15;
        float4 v = make_float4(0.f, 0.f, 0.f, 0.f);
        if (row0 + r < N_NODES)
            v = reinterpret_cast<const float4*>(g_AX + (size_t)(row0 + r) * DIN)[kq];
        sA[(kq * 4 + 0) * 64 + r] = v.x;
        sA[(kq * 4 + 1) * 64 + r] = v.y;
        sA[(kq * 4 + 2) * 64 + r] = v.z;
        sA[(kq * 4 + 3) * 64 + r] = v.w;
    }
    __syncthreads();

    int tc = t & 15, tr = t >> 4;          // 16 col-groups x 8 row-groups
    int c0 = tc * 8, r0 = tr * 8;
    float acc[8][8];
    #pragma unroll
    for (int r = 0; r < 8; r++)
        #pragma unroll
        for (int c = 0; c < 8; c++) acc[r][c] = 0.f;

    #pragma unroll 4
    for (int k = 0; k < DIN; k++) {
        float4 a0 = *reinterpret_cast<float4*>(&sA[k * 64 + r0]);
        float4 a1 = *reinterpret_cast<float4*>(&sA[k * 64 + r0 + 4]);
        float4 q0 = *reinterpret_cast<float4*>(&sB[k * DHID + c0]);
        float4 q1 = *reinterpret_cast<float4*>(&sB[k * DHID + c0 + 4]);
        float a[8] = {a0.x, a0.y, a0.z, a0.w, a1.x, a1.y, a1.z, a1.w};
        float b[8] = {q0.x, q0.y, q0.z, q0.w, q1.x, q1.y, q1.z, q1.w};
        #pragma unroll
        for (int r = 0; r < 8; r++)
            #pragma unroll
            for (int c = 0; c < 8; c++) acc[r][c] = fmaf(a[r], b[c], acc[r][c]);
    }

    float bias[8];
    #pragma unroll
    for (int c = 0; c < 8; c++) bias[c] = __ldg(&b1[c0 + c]);

    #pragma unroll
    for (int r = 0; r < 8; r++) {
        int grow = row0 + r0 + r;
        if (grow >= N_NODES) break;
        float4 o0, o1;
        o0.x = fmaxf(acc[r][0] + bias[0], 0.f);
        o0.y = fmaxf(acc[r][1] + bias[1], 0.f);
        o0.z = fmaxf(acc[r][2] + bias[2], 0.f);
        o0.w = fmaxf(acc[r][3] + bias[3], 0.f);
        o1.x = fmaxf(acc[r][4] + bias[4], 0.f);
        o1.y = fmaxf(acc[r][5] + bias[5], 0.f);
        o1.z = fmaxf(acc[r][6] + bias[6], 0.f);
        o1.w = fmaxf(acc[r][7] + bias[7], 0.f);
        float* dst = g_H + (size_t)grow * DHID + c0;
        reinterpret_cast<float4*>(dst)[0] = o0;
        reinterpret_cast<float4*>(dst)[1] = o1;
    }
}

// ---------------------------------------------------------------------------
// GEMM2: G[N,64] = H[N,128] @ W2[128,64]; also out = b2 + dinv^2 * G
// Block: 64 rows x 64 cols, 128 threads, each computes 8x4 register tile.
__global__ void __launch_bounds__(128) k_gemm2(const float* __restrict__ W2,
                                               const float* __restrict__ b2,
                                               float* __restrict__ out) {
    __shared__ float sA[DHID * 64];   // [k][row]  32 KB (transposed)
    __shared__ float sB[DHID * DOUT]; // [k][col]  32 KB (W2 already [k][col])
    int t = threadIdx.x;
    int row0 = blockIdx.x * 64;

    for (int i = t; i < DHID * DOUT; i += 128) sB[i] = W2[i];
    for (int i = t; i < 64 * 32; i += 128) {       // 64 rows x 32 float4 (k=128)
        int r = i >> 5, kq = i & 31;
        float4 v = make_float4(0.f, 0.f, 0.f, 0.f);
        if (row0 + r < N_NODES)
            v = reinterpret_cast<const float4*>(g_H + (size_t)(row0 + r) * DHID)[kq];
        sA[(kq * 4 + 0) * 64 + r] = v.x;
        sA[(kq * 4 + 1) * 64 + r] = v.y;
        sA[(kq * 4 + 2) * 64 + r] = v.z;
        sA[(kq * 4 + 3) * 64 + r] = v.w;
    }
    __syncthreads();

    int tc = t & 15, tr = t >> 4;          // 16 col-groups x 8 row-groups
    int c0 = tc * 4, r0 = tr * 8;
    float acc[8][4];
    #pragma unroll
    for (int r = 0; r < 8; r++)
        #pragma unroll
        for (int c = 0; c < 4; c++) acc[r][c] = 0.f;

    #pragma unroll 4
    for (int k = 0; k < DHID; k++) {
        float4 a0 = *reinterpret_cast<float4*>(&sA[k * 64 + r0]);
        float4 a1 = *reinterpret_cast<float4*>(&sA[k * 64 + r0 + 4]);
        float4 q0 = *reinterpret_cast<float4*>(&sB[k * DOUT + c0]);
        float a[8] = {a0.x, a0.y, a0.z, a0.w, a1.x, a1.y, a1.z, a1.w};
        float b[4] = {q0.x, q0.y, q0.z, q0.w};
        #pragma unroll
        for (int r = 0; r < 8; r++)
            #pragma unroll
            for (int c = 0; c < 4; c++) acc[r][c] = fmaf(a[r], b[c], acc[r][c]);
    }

    float bias[4];
    #pragma unroll
    for (int c = 0; c < 4; c++) bias[c] = __ldg(&b2[c0 + c]);

    #pragma unroll
    for (int r = 0; r < 8; r++) {
        int grow = row0 + r0 + r;
        if (grow >= N_NODES) break;
        float di = g_dinv[grow];
        float s = di * di;
        float4 gv = make_float4(acc[r][0], acc[r][1], acc[r][2], acc[r][3]);
        reinterpret_cast<float4*>(g_G + (size_t)grow * DOUT + c0)[0] = gv;
        float4 ov;
        ov.x = fmaf(gv.x, s, bias[0]);
        ov.y = fmaf(gv.y, s, bias[1]);
        ov.z = fmaf(gv.z, s, bias[2]);
        ov.w = fmaf(gv.w, s, bias[3]);
        reinterpret_cast<float4*>(out + (size_t)grow * DOUT + c0)[0] = ov;
    }
}

// Scatter layer 2: 16 lanes per edge, red into out
__global__ void k_scatter2(const int* __restrict__ src, const int* __restrict__ dst,
                           float* __restrict__ out) {
    int g = blockIdx.x * blockDim.x + threadIdx.x;
    int e = g >> 4;
    if (e >= N_EDGES) return;
    int l = g & 15;
    int s = src[e], d = dst[e];
    float norm = g_dinv[s] * g_dinv[d];
    float4 v = reinterpret_cast<const float4*>(g_G + (size_t)s * DOUT)[l];
    v.x *= norm; v.y *= norm; v.z *= norm; v.w *= norm;
    red_v4(out + (size_t)d * DOUT + l * 4, v);
}

// ---------------------------------------------------------------------------
extern "C" void kernel_launch(void* const* d_in, const int* in_sizes, int n_in,
                              void* d_out, int out_size) {
    const float* x  = (const float*)d_in[0];
    const int*   ei = (const int*)d_in[1];      // [2, E]
    const float* W1 = (const float*)d_in[2];
    const float* b1 = (const float*)d_in[3];
    const float* W2 = (const float*)d_in[4];
    const float* b2 = (const float*)d_in[5];
    float* out = (float*)d_out;

    const int* src = ei;
    const int* dst = ei + N_EDGES;

    k_init_deg <<<(N_NODES + 255) / 256, 256>>>();
    k_count_deg<<<(N_EDGES + 255) / 256, 256>>>(dst);
    k_dinv     <<<(N_NODES + 255) / 256, 256>>>();

    // layer-1 aggregation on the narrow x (A_hat X), then GEMM
    k_initAX   <<<(N_NODES * (DIN / 4) + 255) / 256, 256>>>(x);
    {
        long long thr = (long long)N_EDGES * 16;
        k_scatterX<<<(unsigned)((thr + 255) / 256), 256>>>(x, src, dst);
    }
    k_gemm1    <<<(N_NODES + 63) / 64, 128>>>(W1, b1);

    // layer 2: GEMM first (reduces 128 -> 64), then aggregate
    k_gemm2    <<<(N_NODES + 63) / 64, 128>>>(W2, b2, out);
    {
        long long thr = (long long)N_EDGES * 16;
        k_scatter2<<<(unsigned)((thr + 255) / 256), 256>>>(src, dst, out);
    }
}

// round 6
// speedup vs baseline: 1.6423x; 1.1994x over previous
#include <cuda_runtime.h>
#include <cuda_bf16.h>

// ---------------------------------------------------------------------------
// GNN_23630910062676: 2-layer GCN, pull-based aggregation via CSR.
//   degi = in-degree histogram -> off = exclusive scan -> col = bucket fill
//   AX[n] = dinv[n]*(dinv[n]*x[n] + sum_s dinv[s]*x[s])        (pull, no atomics)
//   H = relu(AX @ W1 + b1)
//   G = H @ W2
//   out[n] = b2 + dinv[n]*(dinv[n]*G[n] + sum_s dinv[s]*G[s])  (pull, no atomics)
// ---------------------------------------------------------------------------

#define N_NODES 50000
#define N_EDGES 800000
#define DIN  64
#define DHID 128
#define DOUT 64

#define SCAN_BS 512
#define SCAN_NB ((N_NODES + SCAN_BS - 1) / SCAN_BS)   // 98

__device__ int   g_degi[N_NODES];
__device__ int   g_off [N_NODES + 1];
__device__ int   g_cur [N_NODES];
__device__ int   g_bsum[SCAN_NB];
__device__ int   g_col [N_EDGES];
__device__ float g_dinv[N_NODES];
__device__ float g_AX  [N_NODES * DIN];
__device__ float g_H   [N_NODES * DHID];
__device__ float g_G   [N_NODES * DOUT];

// ---------------------------------------------------------------------------
__global__ void k_zero_deg() {
    int i = blockIdx.x * blockDim.x + threadIdx.x;
    if (i < N_NODES) g_degi[i] = 0;
}

__global__ void k_count(const int* __restrict__ dst) {
    int e = blockIdx.x * blockDim.x + threadIdx.x;
    if (e < N_EDGES) atomicAdd(&g_degi[dst[e]], 1);
}

// Per-block inclusive scan (Hillis-Steele), writes block-exclusive + block sums
__global__ void k_scan1() {
    __shared__ int sh[SCAN_BS];
    int gid = blockIdx.x * SCAN_BS + threadIdx.x;
    int v = (gid < N_NODES) ? g_degi[gid] : 0;
    sh[threadIdx.x] = v;
    __syncthreads();
    #pragma unroll
    for (int off = 1; off < SCAN_BS; off <<= 1) {
        int t = (threadIdx.x >= off) ? sh[threadIdx.x - off] : 0;
        __syncthreads();
        sh[threadIdx.x] += t;
        __syncthreads();
    }
    if (gid < N_NODES) g_off[gid] = sh[threadIdx.x] - v;   // exclusive within block
    if (threadIdx.x == SCAN_BS - 1) g_bsum[blockIdx.x] = sh[SCAN_BS - 1];
}

// Serial scan of 98 block sums (single thread; trivial)
__global__ void k_scan2() {
    int acc = 0;
    for (int i = 0; i < SCAN_NB; i++) { int v = g_bsum[i]; g_bsum[i] = acc; acc += v; }
}

// Finalize offsets, init cursors, compute dinv (deg includes self-loop)
__global__ void k_scan3() {
    int i = blockIdx.x * blockDim.x + threadIdx.x;
    if (i < N_NODES) {
        int o = g_off[i] + g_bsum[i / SCAN_BS];
        g_off[i] = o;
        g_cur[i] = o;
        g_dinv[i] = rsqrtf((float)(g_degi[i] + 1));
    }
    if (i == 0) g_off[N_NODES] = N_EDGES;
}

__global__ void k_fill(const int* __restrict__ src, const int* __restrict__ dst) {
    int e = blockIdx.x * blockDim.x + threadIdx.x;
    if (e >= N_EDGES) return;
    int p = atomicAdd(&g_cur[dst[e]], 1);
    g_col[p] = src[e];
}

// ---------------------------------------------------------------------------
// Pull aggregation over a 64-wide tensor: 16 lanes per node, 1 float4/lane.
// acc = dn*(dn*src[n] + sum_s ds*src[s])  (+ optional bias for the output layer)
__global__ void __launch_bounds__(256) k_aggX(const float* __restrict__ x) {
    int n = blockIdx.x * 16 + (threadIdx.x >> 4);
    if (n >= N_NODES) return;
    int l = threadIdx.x & 15;
    const float4* x4 = reinterpret_cast<const float4*>(x);
    float dn = g_dinv[n];
    float4 v = x4[(size_t)n * 16 + l];
    float4 acc = make_float4(v.x * dn, v.y * dn, v.z * dn, v.w * dn);
    int e = g_off[n], end = g_off[n + 1];
    for (; e < end; e++) {
        int s = g_col[e];                 // broadcast across the 16 lanes
        float ds = g_dinv[s];
        float4 u = x4[(size_t)s * 16 + l];
        acc.x = fmaf(u.x, ds, acc.x);
        acc.y = fmaf(u.y, ds, acc.y);
        acc.z = fmaf(u.z, ds, acc.z);
        acc.w = fmaf(u.w, ds, acc.w);
    }
    acc.x *= dn; acc.y *= dn; acc.z *= dn; acc.w *= dn;
    reinterpret_cast<float4*>(g_AX)[(size_t)n * 16 + l] = acc;
}

__global__ void __launch_bounds__(256) k_agg2(const float* __restrict__ b2,
                                              float* __restrict__ out) {
    int n = blockIdx.x * 16 + (threadIdx.x >> 4);
    if (n >= N_NODES) return;
    int l = threadIdx.x & 15;
    const float4* G4 = reinterpret_cast<const float4*>(g_G);
    float dn = g_dinv[n];
    float4 v = G4[(size_t)n * 16 + l];
    float4 acc = make_float4(v.x * dn, v.y * dn, v.z * dn, v.w * dn);
    int e = g_off[n], end = g_off[n + 1];
    for (; e < end; e++) {
        int s = g_col[e];
        float ds = g_dinv[s];
        float4 u = G4[(size_t)s * 16 + l];
        acc.x = fmaf(u.x, ds, acc.x);
        acc.y = fmaf(u.y, ds, acc.y);
        acc.z = fmaf(u.z, ds, acc.z);
        acc.w = fmaf(u.w, ds, acc.w);
    }
    float4 bb = reinterpret_cast<const float4*>(b2)[l];
    float4 o;
    o.x = fmaf(acc.x, dn, bb.x);
    o.y = fmaf(acc.y, dn, bb.y);
    o.z = fmaf(acc.z, dn, bb.z);
    o.w = fmaf(acc.w, dn, bb.w);
    reinterpret_cast<float4*>(out)[(size_t)n * 16 + l] = o;
}

// ---------------------------------------------------------------------------
// GEMM1: H[N,128] = relu(AX[N,64] @ W1[64,128] + b1)
// Block: 64 rows x 128 cols, 128 threads, 8x8 register tile each.
__global__ void __launch_bounds__(128) k_gemm1(const float* __restrict__ W1,
                                               const float* __restrict__ b1) {
    __shared__ float sA[DIN * 64];    // [k][row]
    __shared__ float sB[DIN * DHID];  // [k][col]
    int t = threadIdx.x;
    int row0 = blockIdx.x * 64;

    for (int i = t; i < DIN * DHID; i += 128) sB[i] = W1[i];
    for (int i = t; i < 64 * 16; i += 128) {
        int r = i >> 4, kq = i & 15;
        float4 v = make_float4(0.f, 0.f, 0.f, 0.f);
        if (row0 + r < N_NODES)
            v = reinterpret_cast<const float4*>(g_AX + (size_t)(row0 + r) * DIN)[kq];
        sA[(kq * 4 + 0) * 64 + r] = v.x;
        sA[(kq * 4 + 1) * 64 + r] = v.y;
        sA[(kq * 4 + 2) * 64 + r] = v.z;
        sA[(kq * 4 + 3) * 64 + r] = v.w;
    }
    __syncthreads();

    int tc = t & 15, tr = t >> 4;
    int c0 = tc * 8, r0 = tr * 8;
    float acc[8][8];
    #pragma unroll
    for (int r = 0; r < 8; r++)
        #pragma unroll
        for (int c = 0; c < 8; c++) acc[r][c] = 0.f;

    #pragma unroll 4
    for (int k = 0; k < DIN; k++) {
        float4 a0 = *reinterpret_cast<float4*>(&sA[k * 64 + r0]);
        float4 a1 = *reinterpret_cast<float4*>(&sA[k * 64 + r0 + 4]);
        float4 q0 = *reinterpret_cast<float4*>(&sB[k * DHID + c0]);
        float4 q1 = *reinterpret_cast<float4*>(&sB[k * DHID + c0 + 4]);
        float a[8] = {a0.x, a0.y, a0.z, a0.w, a1.x, a1.y, a1.z, a1.w};
        float b[8] = {q0.x, q0.y, q0.z, q0.w, q1.x, q1.y, q1.z, q1.w};
        #pragma unroll
        for (int r = 0; r < 8; r++)
            #pragma unroll
            for (int c = 0; c < 8; c++) acc[r][c] = fmaf(a[r], b[c], acc[r][c]);
    }

    float bias[8];
    #pragma unroll
    for (int c = 0; c < 8; c++) bias[c] = __ldg(&b1[c0 + c]);

    #pragma unroll
    for (int r = 0; r < 8; r++) {
        int grow = row0 + r0 + r;
        if (grow >= N_NODES) break;
        float4 o0, o1;
        o0.x = fmaxf(acc[r][0] + bias[0], 0.f);
        o0.y = fmaxf(acc[r][1] + bias[1], 0.f);
        o0.z = fmaxf(acc[r][2] + bias[2], 0.f);
        o0.w = fmaxf(acc[r][3] + bias[3], 0.f);
        o1.x = fmaxf(acc[r][4] + bias[4], 0.f);
        o1.y = fmaxf(acc[r][5] + bias[5], 0.f);
        o1.z = fmaxf(acc[r][6] + bias[6], 0.f);
        o1.w = fmaxf(acc[r][7] + bias[7], 0.f);
        float* dstp = g_H + (size_t)grow * DHID + c0;
        reinterpret_cast<float4*>(dstp)[0] = o0;
        reinterpret_cast<float4*>(dstp)[1] = o1;
    }
}

// ---------------------------------------------------------------------------
// GEMM2: G[N,64] = H[N,128] @ W2[128,64]   (epilogue handled by k_agg2)
__global__ void __launch_bounds__(128) k_gemm2(const float* __restrict__ W2) {
    __shared__ float sA[DHID * 64];
    __shared__ float sB[DHID * DOUT];
    int t = threadIdx.x;
    int row0 = blockIdx.x * 64;

    for (int i = t; i < DHID * DOUT; i += 128) sB[i] = W2[i];
    for (int i = t; i < 64 * 32; i += 128) {
        int r = i >> 5, kq = i & 31;
        float4 v = make_float4(0.f, 0.f, 0.f, 0.f);
        if (row0 + r < N_NODES)
            v = reinterpret_cast<const float4*>(g_H + (size_t)(row0 + r) * DHID)[kq];
        sA[(kq * 4 + 0) * 64 + r] = v.x;
        sA[(kq * 4 + 1) * 64 + r] = v.y;
        sA[(kq * 4 + 2) * 64 + r] = v.z;
        sA[(kq * 4 + 3) * 64 + r] = v.w;
    }
    __syncthreads();

    int tc = t & 15, tr = t >> 4;
    int c0 = tc * 4, r0 = tr * 8;
    float acc[8][4];
    #pragma unroll
    for (int r = 0; r < 8; r++)
        #pragma unroll
        for (int c = 0; c < 4; c++) acc[r][c] = 0.f;

    #pragma unroll 4
    for (int k = 0; k < DHID; k++) {
        float4 a0 = *reinterpret_cast<float4*>(&sA[k * 64 + r0]);
        float4 a1 = *reinterpret_cast<float4*>(&sA[k * 64 + r0 + 4]);
        float4 q0 = *reinterpret_cast<float4*>(&sB[k * DOUT + c0]);
        float a[8] = {a0.x, a0.y, a0.z, a0.w, a1.x, a1.y, a1.z, a1.w};
        float b[4] = {q0.x, q0.y, q0.z, q0.w};
        #pragma unroll
        for (int r = 0; r < 8; r++)
            #pragma unroll
            for (int c = 0; c < 4; c++) acc[r][c] = fmaf(a[r], b[c], acc[r][c]);
    }

    #pragma unroll
    for (int r = 0; r < 8; r++) {
        int grow = row0 + r0 + r;
        if (grow >= N_NODES) break;
        float4 gv = make_float4(acc[r][0], acc[r][1], acc[r][2], acc[r][3]);
        reinterpret_cast<float4*>(g_G + (size_t)grow * DOUT + c0)[0] = gv;
    }
}

// ---------------------------------------------------------------------------
extern "C" void kernel_launch(void* const* d_in, const int* in_sizes, int n_in,
                              void* d_out, int out_size) {
    const float* x  = (const float*)d_in[0];
    const int*   ei = (const int*)d_in[1];      // [2, E]
    const float* W1 = (const float*)d_in[2];
    const float* b1 = (const float*)d_in[3];
    const float* W2 = (const float*)d_in[4];
    const float* b2 = (const float*)d_in[5];
    float* out = (float*)d_out;

    const int* src = ei;
    const int* dst = ei + N_EDGES;

    // CSR build (reused by both layers) + dinv
    k_zero_deg<<<(N_NODES + 255) / 256, 256>>>();
    k_count   <<<(N_EDGES + 255) / 256, 256>>>(dst);
    k_scan1   <<<SCAN_NB, SCAN_BS>>>();
    k_scan2   <<<1, 1>>>();
    k_scan3   <<<(N_NODES + 255) / 256, 256>>>();
    k_fill    <<<(N_EDGES + 255) / 256, 256>>>(src, dst);

    // layer 1: pull-aggregate x, then GEMM (+bias+relu fused)
    k_aggX    <<<(N_NODES + 15) / 16, 256>>>(x);
    k_gemm1   <<<(N_NODES + 63) / 64, 128>>>(W1, b1);

    // layer 2: GEMM (128 -> 64), then pull-aggregate into out (+bias fused)
    k_gemm2   <<<(N_NODES + 63) / 64, 128>>>(W2);
    k_agg2    <<<(N_NODES + 15) / 16, 256>>>(b2, out);
}

// round 8
// speedup vs baseline: 1.6673x; 1.0152x over previous
#include <cuda_runtime.h>
#include <cuda_bf16.h>

// ---------------------------------------------------------------------------
// GNN_23630910062676: 2-layer GCN, pull-based aggregation via CSR.
//   degi histogram -> exclusive scan -> bucket fill (CSR by dst)
//   AX[n] = dinv[n]*(dinv[n]*x[n] + sum_s dinv[s]*x[s])        (pull, no atomics)
//   H = relu(AX @ W1 + b1) ; G = H @ W2
//   out[n] = b2 + dinv[n]*(dinv[n]*G[n] + sum_s dinv[s]*G[s])
// R7: 4-way unrolled gather loops (MLP), parallel block-sum scan.
// ---------------------------------------------------------------------------

#define N_NODES 50000
#define N_EDGES 800000
#define DIN  64
#define DHID 128
#define DOUT 64

#define SCAN_BS 512
#define SCAN_NB ((N_NODES + SCAN_BS - 1) / SCAN_BS)   // 98

__device__ int   g_degi[N_NODES];
__device__ int   g_off [N_NODES + 1];
__device__ int   g_cur [N_NODES];
__device__ int   g_bsum[SCAN_NB];
__device__ int   g_col [N_EDGES];
__device__ float g_dinv[N_NODES];
__device__ float g_AX  [N_NODES * DIN];
__device__ float g_H   [N_NODES * DHID];
__device__ float g_G   [N_NODES * DOUT];

// ---------------------------------------------------------------------------
__global__ void k_zero_deg() {
    int i = blockIdx.x * blockDim.x + threadIdx.x;
    if (i < N_NODES) g_degi[i] = 0;
}

__global__ void k_count(const int* __restrict__ dst) {
    int e = blockIdx.x * blockDim.x + threadIdx.x;
    int e2 = e + (N_EDGES / 2);
    if (e < N_EDGES / 2) {
        atomicAdd(&g_degi[dst[e]], 1);
        atomicAdd(&g_degi[dst[e2]], 1);
    }
}

// Per-block inclusive scan, writes block-exclusive + block sums
__global__ void k_scan1() {
    __shared__ int sh[SCAN_BS];
    int gid = blockIdx.x * SCAN_BS + threadIdx.x;
    int v = (gid < N_NODES) ? g_degi[gid] : 0;
    sh[threadIdx.x] = v;
    __syncthreads();
    #pragma unroll
    for (int off = 1; off < SCAN_BS; off <<= 1) {
        int t = (threadIdx.x >= off) ? sh[threadIdx.x - off] : 0;
        __syncthreads();
        sh[threadIdx.x] += t;
        __syncthreads();
    }
    if (gid < N_NODES) g_off[gid] = sh[threadIdx.x] - v;   // exclusive within block
    if (threadIdx.x == SCAN_BS - 1) g_bsum[blockIdx.x] = sh[SCAN_BS - 1];
}

// Parallel exclusive scan of the 98 block sums (one block, smem Hillis-Steele)
__global__ void k_scan2() {
    __shared__ int sh[128];
    int t = threadIdx.x;
    int v = (t < SCAN_NB) ? g_bsum[t] : 0;
    sh[t] = v;
    __syncthreads();
    #pragma unroll
    for (int off = 1; off < 128; off <<= 1) {
        int u = (t >= off) ? sh[t - off] : 0;
        __syncthreads();
        sh[t] += u;
        __syncthreads();
    }
    if (t < SCAN_NB) g_bsum[t] = sh[t] - v;   // exclusive
}

// Finalize offsets, init cursors, compute dinv (deg includes self-loop)
__global__ void k_scan3() {
    int i = blockIdx.x * blockDim.x + threadIdx.x;
    if (i < N_NODES) {
        int o = g_off[i] + g_bsum[i / SCAN_BS];
        g_off[i] = o;
        g_cur[i] = o;
        g_dinv[i] = rsqrtf((float)(g_degi[i] + 1));
    }
    if (i == 0) g_off[N_NODES] = N_EDGES;
}

__global__ void k_fill(const int* __restrict__ src, const int* __restrict__ dst) {
    int e = blockIdx.x * blockDim.x + threadIdx.x;
    int e2 = e + (N_EDGES / 2);
    if (e < N_EDGES / 2) {
        int p  = atomicAdd(&g_cur[dst[e]], 1);
        g_col[p] = src[e];
        int p2 = atomicAdd(&g_cur[dst[e2]], 1);
        g_col[p2] = src[e2];
    }
}

// ---------------------------------------------------------------------------
// Pull aggregation over a 64-wide tensor: 16 lanes per node, 1 float4/lane.
// 4-way unrolled neighbor loop for memory-level parallelism.
#define AGG_BODY(SRC4, SELF_INIT, EPILOGUE)                                     \
    int n = blockIdx.x * 16 + (threadIdx.x >> 4);                               \
    if (n >= N_NODES) return;                                                   \
    int l = threadIdx.x & 15;                                                   \
    float dn = g_dinv[n];                                                       \
    float4 v = (SRC4)[(size_t)n * 16 + l];                                      \
    float4 acc = SELF_INIT;                                                     \
    int e = g_off[n], end = g_off[n + 1];                                       \
    for (; e + 4 <= end; e += 4) {                                              \
        int s0 = g_col[e], s1 = g_col[e + 1], s2 = g_col[e + 2], s3 = g_col[e + 3]; \
        float d0 = g_dinv[s0], d1 = g_dinv[s1], d2 = g_dinv[s2], d3 = g_dinv[s3];   \
        float4 u0 = (SRC4)[(size_t)s0 * 16 + l];                                \
        float4 u1 = (SRC4)[(size_t)s1 * 16 + l];                                \
        float4 u2 = (SRC4)[(size_t)s2 * 16 + l];                                \
        float4 u3 = (SRC4)[(size_t)s3 * 16 + l];                                \
        acc.x = fmaf(u0.x, d0, acc.x); acc.y = fmaf(u0.y, d0, acc.y);           \
        acc.z = fmaf(u0.z, d0, acc.z); acc.w = fmaf(u0.w, d0, acc.w);           \
        acc.x = fmaf(u1.x, d1, acc.x); acc.y = fmaf(u1.y, d1, acc.y);           \
        acc.z = fmaf(u1.z, d1, acc.z); acc.w = fmaf(u1.w, d1, acc.w);           \
        acc.x = fmaf(u2.x, d2, acc.x); acc.y = fmaf(u2.y, d2, acc.y);           \
        acc.z = fmaf(u2.z, d2, acc.z); acc.w = fmaf(u2.w, d2, acc.w);           \
        acc.x = fmaf(u3.x, d3, acc.x); acc.y = fmaf(u3.y, d3, acc.y);           \
        acc.z = fmaf(u3.z, d3, acc.z); acc.w = fmaf(u3.w, d3, acc.w);           \
    }                                                                           \
    for (; e < end; e++) {                                                      \
        int s = g_col[e];                                                       \
        float ds = g_dinv[s];                                                   \
        float4 u = (SRC4)[(size_t)s * 16 + l];                                  \
        acc.x = fmaf(u.x, ds, acc.x); acc.y = fmaf(u.y, ds, acc.y);             \
        acc.z = fmaf(u.z, ds, acc.z); acc.w = fmaf(u.w, ds, acc.w);             \
    }                                                                           \
    EPILOGUE

__global__ void __launch_bounds__(256) k_aggX(const float* __restrict__ x) {
    const float4* x4 = reinterpret_cast<const float4*>(x);
    AGG_BODY(x4,
             make_float4(v.x * dn, v.y * dn, v.z * dn, v.w * dn),
             {
                 acc.x *= dn; acc.y *= dn; acc.z *= dn; acc.w *= dn;
                 reinterpret_cast<float4*>(g_AX)[(size_t)n * 16 + l] = acc;
             })
}

__global__ void __launch_bounds__(256) k_agg2(const float* __restrict__ b2,
                                              float* __restrict__ out) {
    const float4* G4 = reinterpret_cast<const float4*>(g_G);
    AGG_BODY(G4,
             make_float4(v.x * dn, v.y * dn, v.z * dn, v.w * dn),
             {
                 float4 bb = reinterpret_cast<const float4*>(b2)[l];
                 float4 o;
                 o.x = fmaf(acc.x, dn, bb.x);
                 o.y = fmaf(acc.y, dn, bb.y);
                 o.z = fmaf(acc.z, dn, bb.z);
                 o.w = fmaf(acc.w, dn, bb.w);
                 reinterpret_cast<float4*>(out)[(size_t)n * 16 + l] = o;
             })
}

// ---------------------------------------------------------------------------
// GEMM1: H[N,128] = relu(AX[N,64] @ W1[64,128] + b1)
// Block: 64 rows x 128 cols, 128 threads, 8x8 register tile each.
__global__ void __launch_bounds__(128) k_gemm1(const float* __restrict__ W1,
                                               const float* __restrict__ b1) {
    __shared__ float sA[DIN * 64];    // [k][row]
    __shared__ float sB[DIN * DHID];  // [k][col]
    int t = threadIdx.x;
    int row0 = blockIdx.x * 64;

    for (int i = t; i < DIN * DHID; i += 128) sB[i] = W1[i];
    for (int i = t; i < 64 * 16; i += 128) {
        int r = i >> 4, kq = i & 15;
        float4 v = make_float4(0.f, 0.f, 0.f, 0.f);
        if (row0 + r < N_NODES)
            v = reinterpret_cast<const float4*>(g_AX + (size_t)(row0 + r) * DIN)[kq];
        sA[(kq * 4 + 0) * 64 + r] = v.x;
        sA[(kq * 4 + 1) * 64 + r] = v.y;
        sA[(kq * 4 + 2) * 64 + r] = v.z;
        sA[(kq * 4 + 3) * 64 + r] = v.w;
    }
    __syncthreads();

    int tc = t & 15, tr = t >> 4;
    int c0 = tc * 8, r0 = tr * 8;
    float acc[8][8];
    #pragma unroll
    for (int r = 0; r < 8; r++)
        #pragma unroll
        for (int c = 0; c < 8; c++) acc[r][c] = 0.f;

    #pragma unroll 4
    for (int k = 0; k < DIN; k++) {
        float4 a0 = *reinterpret_cast<float4*>(&sA[k * 64 + r0]);
        float4 a1 = *reinterpret_cast<float4*>(&sA[k * 64 + r0 + 4]);
        float4 q0 = *reinterpret_cast<float4*>(&sB[k * DHID + c0]);
        float4 q1 = *reinterpret_cast<float4*>(&sB[k * DHID + c0 + 4]);
        float a[8] = {a0.x, a0.y, a0.z, a0.w, a1.x, a1.y, a1.z, a1.w};
        float b[8] = {q0.x, q0.y, q0.z, q0.w, q1.x, q1.y, q1.z, q1.w};
        #pragma unroll
        for (int r = 0; r < 8; r++)
            #pragma unroll
            for (int c = 0; c < 8; c++) acc[r][c] = fmaf(a[r], b[c], acc[r][c]);
    }

    float bias[8];
    #pragma unroll
    for (int c = 0; c < 8; c++) bias[c] = __ldg(&b1[c0 + c]);

    #pragma unroll
    for (int r = 0; r < 8; r++) {
        int grow = row0 + r0 + r;
        if (grow >= N_NODES) break;
        float4 o0, o1;
        o0.x = fmaxf(acc[r][0] + bias[0], 0.f);
        o0.y = fmaxf(acc[r][1] + bias[1], 0.f);
        o0.z = fmaxf(acc[r][2] + bias[2], 0.f);
        o0.w = fmaxf(acc[r][3] + bias[3], 0.f);
        o1.x = fmaxf(acc[r][4] + bias[4], 0.f);
        o1.y = fmaxf(acc[r][5] + bias[5], 0.f);
        o1.z = fmaxf(acc[r][6] + bias[6], 0.f);
        o1.w = fmaxf(acc[r][7] + bias[7], 0.f);
        float* dstp = g_H + (size_t)grow * DHID + c0;
        reinterpret_cast<float4*>(dstp)[0] = o0;
        reinterpret_cast<float4*>(dstp)[1] = o1;
    }
}

// ---------------------------------------------------------------------------
// GEMM2: G[N,64] = H[N,128] @ W2[128,64]   (epilogue handled by k_agg2)
__global__ void __launch_bounds__(128) k_gemm2(const float* __restrict__ W2) {
    __shared__ float sA[DHID * 64];
    __shared__ float sB[DHID * DOUT];
    int t = threadIdx.x;
    int row0 = blockIdx.x * 64;

    for (int i = t; i < DHID * DOUT; i += 128) sB[i] = W2[i];
    for (int i = t; i < 64 * 32; i += 128) {
        int r = i >> 5, kq = i & 31;
        float4 v = make_float4(0.f, 0.f, 0.f, 0.f);
        if (row0 + r < N_NODES)
            v = reinterpret_cast<const float4*>(g_H + (size_t)(row0 + r) * DHID)[kq];
        sA[(kq * 4 + 0) * 64 + r] = v.x;
        sA[(kq * 4 + 1) * 64 + r] = v.y;
        sA[(kq * 4 + 2) * 64 + r] = v.z;
        sA[(kq * 4 + 3) * 64 + r] = v.w;
    }
    __syncthreads();

    int tc = t & 15, tr = t >> 4;
    int c0 = tc * 4, r0 = tr * 8;
    float acc[8][4];
    #pragma unroll
    for (int r = 0; r < 8; r++)
        #pragma unroll
        for (int c = 0; c < 4; c++) acc[r][c] = 0.f;

    #pragma unroll 4
    for (int k = 0; k < DHID; k++) {
        float4 a0 = *reinterpret_cast<float4*>(&sA[k * 64 + r0]);
        float4 a1 = *reinterpret_cast<float4*>(&sA[k * 64 + r0 + 4]);
        float4 q0 = *reinterpret_cast<float4*>(&sB[k * DOUT + c0]);
        float a[8] = {a0.x, a0.y, a0.z, a0.w, a1.x, a1.y, a1.z, a1.w};
        float b[4] = {q0.x, q0.y, q0.z, q0.w};
        #pragma unroll
        for (int r = 0; r < 8; r++)
            #pragma unroll
            for (int c = 0; c < 4; c++) acc[r][c] = fmaf(a[r], b[c], acc[r][c]);
    }

    #pragma unroll
    for (int r = 0; r < 8; r++) {
        int grow = row0 + r0 + r;
        if (grow >= N_NODES) break;
        float4 gv = make_float4(acc[r][0], acc[r][1], acc[r][2], acc[r][3]);
        reinterpret_cast<float4*>(g_G + (size_t)grow * DOUT + c0)[0] = gv;
    }
}

// ---------------------------------------------------------------------------
extern "C" void kernel_launch(void* const* d_in, const int* in_sizes, int n_in,
                              void* d_out, int out_size) {
    const float* x  = (const float*)d_in[0];
    const int*   ei = (const int*)d_in[1];      // [2, E]
    const float* W1 = (const float*)d_in[2];
    const float* b1 = (const float*)d_in[3];
    const float* W2 = (const float*)d_in[4];
    const float* b2 = (const float*)d_in[5];
    float* out = (float*)d_out;

    const int* src = ei;
    const int* dst = ei + N_EDGES;

    // CSR build (reused by both layers) + dinv
    k_zero_deg<<<(N_NODES + 255) / 256, 256>>>();
    k_count   <<<(N_EDGES / 2 + 255) / 256, 256>>>(dst);
    k_scan1   <<<SCAN_NB, SCAN_BS>>>();
    k_scan2   <<<1, 128>>>();
    k_scan3   <<<(N_NODES + 255) / 256, 256>>>();
    k_fill    <<<(N_EDGES / 2 + 255) / 256, 256>>>(src, dst);

    // layer 1: pull-aggregate x, then GEMM (+bias+relu fused)
    k_aggX    <<<(N_NODES + 15) / 16, 256>>>(x);
    k_gemm1   <<<(N_NODES + 63) / 64, 128>>>(W1, b1);

    // layer 2: GEMM (128 -> 64), then pull-aggregate into out (+bias fused)
    k_gemm2   <<<(N_NODES + 63) / 64, 128>>>(W2);
    k_agg2    <<<(N_NODES + 15) / 16, 256>>>(b2, out);
}

// round 11
// speedup vs baseline: 1.8824x; 1.1291x over previous
#include <cuda_runtime.h>
#include <cuda_bf16.h>

// ---------------------------------------------------------------------------
// GNN_23630910062676: 2-layer GCN, pull-based aggregation via CSR.
//   degi histogram -> exclusive scan -> bucket fill (CSR by dst)
//   AX[n] = dinv[n]*(dinv[n]*x[n] + sum_s dinv[s]*x[s])        (pull, no atomics)
//   H = relu(AX @ W1 + b1) ; G = H @ W2
//   out[n] = b2 + dinv[n]*(dinv[n]*G[n] + sum_s dinv[s]*G[s])
// R9: warp-per-node aggregation (no divergence), 128-row GEMM tiles,
//     memsetAsync for the histogram zero.
// ---------------------------------------------------------------------------

#define N_NODES 50000
#define N_EDGES 800000
#define DIN  64
#define DHID 128
#define DOUT 64

#define SCAN_BS 512
#define SCAN_NB ((N_NODES + SCAN_BS - 1) / SCAN_BS)   // 98

__device__ int   g_degi[N_NODES];
__device__ int   g_off [N_NODES + 1];
__device__ int   g_cur [N_NODES];
__device__ int   g_bsum[SCAN_NB];
__device__ int   g_col [N_EDGES];
__device__ float g_dinv[N_NODES];
__device__ float g_AX  [N_NODES * DIN];
__device__ float g_H   [N_NODES * DHID];
__device__ float g_G   [N_NODES * DOUT];

// ---------------------------------------------------------------------------
__global__ void k_count(const int* __restrict__ dst) {
    int e = blockIdx.x * blockDim.x + threadIdx.x;
    int e2 = e + (N_EDGES / 2);
    if (e < N_EDGES / 2) {
        atomicAdd(&g_degi[dst[e]], 1);
        atomicAdd(&g_degi[dst[e2]], 1);
    }
}

// Per-block inclusive scan, writes block-exclusive + block sums
__global__ void k_scan1() {
    __shared__ int sh[SCAN_BS];
    int gid = blockIdx.x * SCAN_BS + threadIdx.x;
    int v = (gid < N_NODES) ? g_degi[gid] : 0;
    sh[threadIdx.x] = v;
    __syncthreads();
    #pragma unroll
    for (int off = 1; off < SCAN_BS; off <<= 1) {
        int t = (threadIdx.x >= off) ? sh[threadIdx.x - off] : 0;
        __syncthreads();
        sh[threadIdx.x] += t;
        __syncthreads();
    }
    if (gid < N_NODES) g_off[gid] = sh[threadIdx.x] - v;   // exclusive within block
    if (threadIdx.x == SCAN_BS - 1) g_bsum[blockIdx.x] = sh[SCAN_BS - 1];
}

// Parallel exclusive scan of the 98 block sums
__global__ void k_scan2() {
    __shared__ int sh[128];
    int t = threadIdx.x;
    int v = (t < SCAN_NB) ? g_bsum[t] : 0;
    sh[t] = v;
    __syncthreads();
    #pragma unroll
    for (int off = 1; off < 128; off <<= 1) {
        int u = (t >= off) ? sh[t - off] : 0;
        __syncthreads();
        sh[t] += u;
        __syncthreads();
    }
    if (t < SCAN_NB) g_bsum[t] = sh[t] - v;   // exclusive
}

// Finalize offsets, init cursors, compute dinv (deg includes self-loop)
__global__ void k_scan3() {
    int i = blockIdx.x * blockDim.x + threadIdx.x;
    if (i < N_NODES) {
        int o = g_off[i] + g_bsum[i / SCAN_BS];
        g_off[i] = o;
        g_cur[i] = o;
        g_dinv[i] = rsqrtf((float)(g_degi[i] + 1));
    }
    if (i == 0) g_off[N_NODES] = N_EDGES;
}

__global__ void k_fill(const int* __restrict__ src, const int* __restrict__ dst) {
    int e = blockIdx.x * blockDim.x + threadIdx.x;
    int e2 = e + (N_EDGES / 2);
    if (e < N_EDGES / 2) {
        int p  = atomicAdd(&g_cur[dst[e]], 1);
        g_col[p] = src[e];
        int p2 = atomicAdd(&g_cur[dst[e2]], 1);
        g_col[p2] = src[e2];
    }
}

// ---------------------------------------------------------------------------
// Pull aggregation over a 64-wide tensor: ONE WARP per node, float2 per lane.
// No intra-warp divergence; 4-way unrolled neighbor loop for MLP.
#define AGG_BODY(SRC2, EPILOGUE)                                                \
    int n = blockIdx.x * 8 + (threadIdx.x >> 5);                                \
    if (n >= N_NODES) return;                                                   \
    int l = threadIdx.x & 31;                                                   \
    float dn = g_dinv[n];                                                       \
    float2 v = (SRC2)[(size_t)n * 32 + l];                                      \
    float ax = v.x * dn, ay = v.y * dn;                                         \
    int e = g_off[n], end = g_off[n + 1];                                       \
    for (; e + 4 <= end; e += 4) {                                              \
        int s0 = g_col[e], s1 = g_col[e + 1], s2 = g_col[e + 2], s3 = g_col[e + 3]; \
        float d0 = g_dinv[s0], d1 = g_dinv[s1], d2 = g_dinv[s2], d3 = g_dinv[s3];   \
        float2 u0 = (SRC2)[(size_t)s0 * 32 + l];                                \
        float2 u1 = (SRC2)[(size_t)s1 * 32 + l];                                \
        float2 u2 = (SRC2)[(size_t)s2 * 32 + l];                                \
        float2 u3 = (SRC2)[(size_t)s3 * 32 + l];                                \
        ax = fmaf(u0.x, d0, ax); ay = fmaf(u0.y, d0, ay);                       \
        ax = fmaf(u1.x, d1, ax); ay = fmaf(u1.y, d1, ay);                       \
        ax = fmaf(u2.x, d2, ax); ay = fmaf(u2.y, d2, ay);                       \
        ax = fmaf(u3.x, d3, ax); ay = fmaf(u3.y, d3, ay);                       \
    }                                                                           \
    for (; e < end; e++) {                                                      \
        int s = g_col[e];                                                       \
        float ds = g_dinv[s];                                                   \
        float2 u = (SRC2)[(size_t)s * 32 + l];                                  \
        ax = fmaf(u.x, ds, ax); ay = fmaf(u.y, ds, ay);                         \
    }                                                                           \
    EPILOGUE

__global__ void __launch_bounds__(256) k_aggX(const float* __restrict__ x) {
    const float2* x2 = reinterpret_cast<const float2*>(x);
    AGG_BODY(x2,
             {
                 float2 o = make_float2(ax * dn, ay * dn);
                 reinterpret_cast<float2*>(g_AX)[(size_t)n * 32 + l] = o;
             })
}

__global__ void __launch_bounds__(256) k_agg2(const float* __restrict__ b2,
                                              float* __restrict__ out) {
    const float2* G2 = reinterpret_cast<const float2*>(g_G);
    AGG_BODY(G2,
             {
                 float2 bb = reinterpret_cast<const float2*>(b2)[l];
                 float2 o = make_float2(fmaf(ax, dn, bb.x), fmaf(ay, dn, bb.y));
                 reinterpret_cast<float2*>(out)[(size_t)n * 32 + l] = o;
             })
}

// ---------------------------------------------------------------------------
// GEMM1: H[N,128] = relu(AX[N,64] @ W1[64,128] + b1)
// Block: 128 rows x 128 cols, 256 threads, 8x8 register tile each.
__global__ void __launch_bounds__(256) k_gemm1(const float* __restrict__ W1,
                                               const float* __restrict__ b1) {
    __shared__ float sA[DIN * 128];   // [k][row] 32 KB
    __shared__ float sB[DIN * DHID];  // [k][col] 32 KB
    int t = threadIdx.x;
    int row0 = blockIdx.x * 128;

    for (int i = t; i < DIN * DHID; i += 256) sB[i] = W1[i];
    for (int i = t; i < 128 * 16; i += 256) {       // 128 rows x 16 float4
        int r = i >> 4, kq = i & 15;
        float4 v = make_float4(0.f, 0.f, 0.f, 0.f);
        if (row0 + r < N_NODES)
            v = reinterpret_cast<const float4*>(g_AX + (size_t)(row0 + r) * DIN)[kq];
        sA[(kq * 4 + 0) * 128 + r] = v.x;
        sA[(kq * 4 + 1) * 128 + r] = v.y;
        sA[(kq * 4 + 2) * 128 + r] = v.z;
        sA[(kq * 4 + 3) * 128 + r] = v.w;
    }
    __syncthreads();

    int tc = t & 15, tr = t >> 4;          // 16 col-groups x 16 row-groups
    int c0 = tc * 8, r0 = tr * 8;
    float acc[8][8];
    #pragma unroll
    for (int r = 0; r < 8; r++)
        #pragma unroll
        for (int c = 0; c < 8; c++) acc[r][c] = 0.f;

    #pragma unroll 4
    for (int k = 0; k < DIN; k++) {
        float4 a0 = *reinterpret_cast<float4*>(&sA[k * 128 + r0]);
        float4 a1 = *reinterpret_cast<float4*>(&sA[k * 128 + r0 + 4]);
        float4 q0 = *reinterpret_cast<float4*>(&sB[k * DHID + c0]);
        float4 q1 = *reinterpret_cast<float4*>(&sB[k * DHID + c0 + 4]);
        float a[8] = {a0.x, a0.y, a0.z, a0.w, a1.x, a1.y, a1.z, a1.w};
        float b[8] = {q0.x, q0.y, q0.z, q0.w, q1.x, q1.y, q1.z, q1.w};
        #pragma unroll
        for (int r = 0; r < 8; r++)
            #pragma unroll
            for (int c = 0; c < 8; c++) acc[r][c] = fmaf(a[r], b[c], acc[r][c]);
    }

    float bias[8];
    #pragma unroll
    for (int c = 0; c < 8; c++) bias[c] = __ldg(&b1[c0 + c]);

    #pragma unroll
    for (int r = 0; r < 8; r++) {
        int grow = row0 + r0 + r;
        if (grow >= N_NODES) break;
        float4 o0, o1;
        o0.x = fmaxf(acc[r][0] + bias[0], 0.f);
        o0.y = fmaxf(acc[r][1] + bias[1], 0.f);
        o0.z = fmaxf(acc[r][2] + bias[2], 0.f);
        o0.w = fmaxf(acc[r][3] + bias[3], 0.f);
        o1.x = fmaxf(acc[r][4] + bias[4], 0.f);
        o1.y = fmaxf(acc[r][5] + bias[5], 0.f);
        o1.z = fmaxf(acc[r][6] + bias[6], 0.f);
        o1.w = fmaxf(acc[r][7] + bias[7], 0.f);
        float* dstp = g_H + (size_t)grow * DHID + c0;
        reinterpret_cast<float4*>(dstp)[0] = o0;
        reinterpret_cast<float4*>(dstp)[1] = o1;
    }
}

// ---------------------------------------------------------------------------
// GEMM2: G[N,64] = H[N,128] @ W2[128,64]
// Block: 128 rows x 64 cols, 256 threads, 8x4 tile, K in two 64-chunks.
__global__ void __launch_bounds__(256) k_gemm2(const float* __restrict__ W2) {
    __shared__ float sA[64 * 128];    // [k-chunk][row] 32 KB
    __shared__ float sB[DHID * DOUT]; // [k][col] 32 KB
    int t = threadIdx.x;
    int row0 = blockIdx.x * 128;

    for (int i = t; i < DHID * DOUT; i += 256) sB[i] = W2[i];

    int tc = t & 15, tr = t >> 4;          // 16 col-groups x 16 row-groups
    int c0 = tc * 4, r0 = tr * 8;
    float acc[8][4];
    #pragma unroll
    for (int r = 0; r < 8; r++)
        #pragma unroll
        for (int c = 0; c < 4; c++) acc[r][c] = 0.f;

    #pragma unroll
    for (int ch = 0; ch < 2; ch++) {
        __syncthreads();   // sB ready (ch=0) / sA reuse safe (ch=1)
        for (int i = t; i < 128 * 16; i += 256) {   // 128 rows x 16 float4 of this chunk
            int r = i >> 4, kq = i & 15;
            float4 v = make_float4(0.f, 0.f, 0.f, 0.f);
            if (row0 + r < N_NODES)
                v = reinterpret_cast<const float4*>(g_H + (size_t)(row0 + r) * DHID)
                        [ch * 16 + kq];
            sA[(kq * 4 + 0) * 128 + r] = v.x;
            sA[(kq * 4 + 1) * 128 + r] = v.y;
            sA[(kq * 4 + 2) * 128 + r] = v.z;
            sA[(kq * 4 + 3) * 128 + r] = v.w;
        }
        __syncthreads();

        #pragma unroll 4
        for (int k = 0; k < 64; k++) {
            float4 a0 = *reinterpret_cast<float4*>(&sA[k * 128 + r0]);
            float4 a1 = *reinterpret_cast<float4*>(&sA[k * 128 + r0 + 4]);
            float4 q0 = *reinterpret_cast<float4*>(&sB[(ch * 64 + k) * DOUT + c0]);
            float a[8] = {a0.x, a0.y, a0.z, a0.w, a1.x, a1.y, a1.z, a1.w};
            float b[4] = {q0.x, q0.y, q0.z, q0.w};
            #pragma unroll
            for (int r = 0; r < 8; r++)
                #pragma unroll
                for (int c = 0; c < 4; c++) acc[r][c] = fmaf(a[r], b[c], acc[r][c]);
        }
    }

    #pragma unroll
    for (int r = 0; r < 8; r++) {
        int grow = row0 + r0 + r;
        if (grow >= N_NODES) break;
        float4 gv = make_float4(acc[r][0], acc[r][1], acc[r][2], acc[r][3]);
        reinterpret_cast<float4*>(g_G + (size_t)grow * DOUT + c0)[0] = gv;
    }
}

// ---------------------------------------------------------------------------
extern "C" void kernel_launch(void* const* d_in, const int* in_sizes, int n_in,
                              void* d_out, int out_size) {
    const float* x  = (const float*)d_in[0];
    const int*   ei = (const int*)d_in[1];      // [2, E]
    const float* W1 = (const float*)d_in[2];
    const float* b1 = (const float*)d_in[3];
    const float* W2 = (const float*)d_in[4];
    const float* b2 = (const float*)d_in[5];
    float* out = (float*)d_out;

    const int* src = ei;
    const int* dst = ei + N_EDGES;

    // CSR build (reused by both layers) + dinv
    int* degi_ptr = nullptr;
    cudaGetSymbolAddress((void**)&degi_ptr, g_degi);
    cudaMemsetAsync(degi_ptr, 0, N_NODES * sizeof(int));

    k_count   <<<(N_EDGES / 2 + 255) / 256, 256>>>(dst);
    k_scan1   <<<SCAN_NB, SCAN_BS>>>();
    k_scan2   <<<1, 128>>>();
    k_scan3   <<<(N_NODES + 255) / 256, 256>>>();
    k_fill    <<<(N_EDGES / 2 + 255) / 256, 256>>>(src, dst);

    // layer 1: pull-aggregate x, then GEMM (+bias+relu fused)
    k_aggX    <<<(N_NODES + 7) / 8, 256>>>(x);
    k_gemm1   <<<(N_NODES + 127) / 128, 256>>>(W1, b1);

    // layer 2: GEMM (128 -> 64), then pull-aggregate into out (+bias fused)
    k_gemm2   <<<(N_NODES + 127) / 128, 256>>>(W2);
    k_agg2    <<<(N_NODES + 7) / 8, 256>>>(b2, out);
}